// round 13
// baseline (speedup 1.0000x reference)
#include <cuda_runtime.h>

#define NN 16384
#define CAP 96

// Scratch (no allocations). Referenced ONLY from device code.
__device__ int   g_cnt[NN];
__device__ int   g_nbr[NN * CAP];
__device__ float g_z0[NN * 128];
__device__ float g_r0[NN * 128];
__device__ float g_z1[NN * 128];
__device__ float g_r1[NN * 128];
__device__ float g_z2[NN * 64];
__device__ float g_r2[NN * 64];
__device__ float g_h[NN * 128];

__device__ __forceinline__ float* zbuf(int s) { return s == 0 ? g_z0 : (s == 1 ? g_z1 : g_z2); }
__device__ __forceinline__ float* rbuf(int s) { return s == 0 ? g_r0 : (s == 1 ? g_r1 : g_r2); }

__global__ void zero_cnt_kernel() {
    int i = blockIdx.x * blockDim.x + threadIdx.x;
    if (i < NN) g_cnt[i] = 0;
}

__device__ __forceinline__ float4 f4add(float4 a, float4 b) {
    return make_float4(a.x + b.x, a.y + b.y, a.z + b.z, a.w + b.w);
}

// ---------------------------------------------------------------------------
// LOW-REG GEMM block (layer 0, hidden under scan): 64x64 tile of
// x[N,128] @ [Wl0|Wr0]^T (fout=128). BK=32, 256 thr, TM=4xTN=4, ~42 regs.
// ---------------------------------------------------------------------------
__device__ __forceinline__ void gemm_block_small(
    const float* __restrict__ A,
    const float* __restrict__ Wl, const float* __restrict__ Wr,
    const float* __restrict__ bias, int rb, int cb,
    float (*As)[64], float (*Bs)[64])
{
    const int fout = 128;
    int tid = threadIdx.x;
    int rowBase = rb * 64;
    int vcol = cb * 64;

    const float* B;
    float* out;
    int colBase;
    bool addb;
    if (vcol < fout) { B = Wl; out = g_z0; colBase = vcol;        addb = false; }
    else             { B = Wr; out = g_r0; colBase = vcol - fout; addb = true;  }

    int tx = tid & 15;
    int ty = tid >> 4;

    float acc[4][4];
#pragma unroll
    for (int i = 0; i < 4; i++)
#pragma unroll
        for (int j = 0; j < 4; j++) acc[i][j] = 0.0f;

#pragma unroll 1
    for (int kt = 0; kt < 4; kt++) {
        int koff = kt * 32;
#pragma unroll
        for (int i = 0; i < 2; i++) {
            int lin = tid + i * 256;
            int m = lin >> 3;
            int kq = lin & 7;
            float4 v = *reinterpret_cast<const float4*>(
                &A[(size_t)(rowBase + m) * 128 + koff + kq * 4]);
            As[kq * 4 + 0][m] = v.x;
            As[kq * 4 + 1][m] = v.y;
            As[kq * 4 + 2][m] = v.z;
            As[kq * 4 + 3][m] = v.w;
        }
#pragma unroll
        for (int i = 0; i < 2; i++) {
            int lin = tid + i * 256;
            int o = lin >> 3;
            int kq = lin & 7;
            float4 v = *reinterpret_cast<const float4*>(
                &B[(size_t)(colBase + o) * 128 + koff + kq * 4]);
            Bs[kq * 4 + 0][o] = v.x;
            Bs[kq * 4 + 1][o] = v.y;
            Bs[kq * 4 + 2][o] = v.z;
            Bs[kq * 4 + 3][o] = v.w;
        }
        __syncthreads();

#pragma unroll
        for (int kk = 0; kk < 32; kk++) {
            float4 a0 = *reinterpret_cast<float4*>(&As[kk][ty * 4]);
            float4 b0 = *reinterpret_cast<float4*>(&Bs[kk][tx * 4]);
            float am[4] = {a0.x, a0.y, a0.z, a0.w};
            float bn[4] = {b0.x, b0.y, b0.z, b0.w};
#pragma unroll
            for (int i = 0; i < 4; i++)
#pragma unroll
                for (int j = 0; j < 4; j++)
                    acc[i][j] = fmaf(am[i], bn[j], acc[i][j]);
        }
        __syncthreads();
    }

#pragma unroll
    for (int i = 0; i < 4; i++) {
        int m = rowBase + ty * 4 + i;
        int o = colBase + tx * 4;
        float4 v;
        v.x = acc[i][0]; v.y = acc[i][1]; v.z = acc[i][2]; v.w = acc[i][3];
        if (addb) {
            float4 bv = *reinterpret_cast<const float4*>(&bias[o]);
            v.x += bv.x; v.y += bv.y; v.z += bv.z; v.w += bv.w;
        }
        *reinterpret_cast<float4*>(&out[(size_t)m * fout + o]) = v;
    }
}

// ---------------------------------------------------------------------------
// Fused kernel (R11-proven): blocks [0,1024) = layer-0 transform (lean regs);
// blocks [1024, 1024+32768) scan the 1 GB adj (32 KB contiguous per block).
// ---------------------------------------------------------------------------
__global__ void __launch_bounds__(256) fused_gemm0_build_kernel(
    const float* __restrict__ x, const float* __restrict__ adj,
    const float* __restrict__ Wl0, const float* __restrict__ Wr0,
    const float* __restrict__ b0)
{
    __shared__ float As[32][64];
    __shared__ float Bs[32][64];

    int bid = blockIdx.x;
    if (bid < 1024) {
        gemm_block_small(x, Wl0, Wr0, b0, bid >> 2, bid & 3, As, Bs);
        return;
    }

    int bb = bid - 1024;
    const float4* adj4 = reinterpret_cast<const float4*>(adj);
    size_t base = (size_t)bb * 2048 + threadIdx.x;

    float4 v[8];
#pragma unroll
    for (int i = 0; i < 8; i++) v[i] = __ldcs(&adj4[base + (size_t)i * 256]);

#pragma unroll
    for (int i = 0; i < 8; i++) {
        size_t idx = base + (size_t)i * 256;
        int r  = (int)(idx >> 12);          // 4096 float4 per adj row
        int c0 = (int)((idx & 4095) << 2);
        if (v[i].x != 0.0f) { int s = atomicAdd(&g_cnt[c0 + 0], 1); if (s < CAP) g_nbr[(c0 + 0) * CAP + s] = r; }
        if (v[i].y != 0.0f) { int s = atomicAdd(&g_cnt[c0 + 1], 1); if (s < CAP) g_nbr[(c0 + 1) * CAP + s] = r; }
        if (v[i].z != 0.0f) { int s = atomicAdd(&g_cnt[c0 + 2], 1); if (s < CAP) g_nbr[(c0 + 2) * CAP + s] = r; }
        if (v[i].w != 0.0f) { int s = atomicAdd(&g_cnt[c0 + 3], 1); if (s < CAP) g_nbr[(c0 + 3) * CAP + s] = r; }
    }
}

// ---------------------------------------------------------------------------
// Fused layer kernel (phase fusion): block b owns rows [b*128, b*128+128).
// Phase 1 (all 512 threads): gather those 128 h-rows from z[zin]/r[zin]
//   (relu) into g_h — the ONLY consumer is this block's phase 2.
// Phase 2: 128 x VC double-buffered gemm (BK=8, single sync per k-tile):
//   [z|r](zout) = h @ [Wl|Wr]^T (+bias on r half).
// VC = 2*fout (256 for layer 1, 128 for layer 2).
// ---------------------------------------------------------------------------
template <int VC>
__global__ void __launch_bounds__(512) fused_layer_kernel(
    const float* __restrict__ Wl, const float* __restrict__ Wr,
    const float* __restrict__ bias, int fout, int zin, int zout)
{
    constexpr int TN = VC / 32;          // 8 (VC=256) or 4 (VC=128)
    constexpr int BPAD = VC + 4;
    __shared__ float As[2][8][132];
    __shared__ float Bs[2][8][BPAD];

    int tid = threadIdx.x;
    int rowBase = blockIdx.x * 128;

    // ---- Phase 1: gather 128 rows -> g_h (relu) ----
    {
        int w = tid >> 5;
        int c = tid & 31;
        const float4* z4 = reinterpret_cast<const float4*>(zbuf(zin));
        const float4* r4 = reinterpret_cast<const float4*>(rbuf(zin));
        float4* h4 = reinterpret_cast<float4*>(g_h);
#pragma unroll 1
        for (int rep = 0; rep < 8; rep++) {
            int t = rowBase + w * 8 + rep;
            int deg = min(g_cnt[t], CAP);
            const int* nb = &g_nbr[t * CAP];
            float4 s = make_float4(0.f, 0.f, 0.f, 0.f);
            int i = 0;
            for (; i + 8 <= deg; i += 8) {
                int4 n0 = *reinterpret_cast<const int4*>(&nb[i]);
                int4 n1 = *reinterpret_cast<const int4*>(&nb[i + 4]);
                float4 a = z4[(size_t)n0.x * 32 + c];
                float4 b = z4[(size_t)n0.y * 32 + c];
                float4 cc = z4[(size_t)n0.z * 32 + c];
                float4 d = z4[(size_t)n0.w * 32 + c];
                float4 e = z4[(size_t)n1.x * 32 + c];
                float4 f = z4[(size_t)n1.y * 32 + c];
                float4 g = z4[(size_t)n1.z * 32 + c];
                float4 h = z4[(size_t)n1.w * 32 + c];
                s = f4add(s, f4add(f4add(f4add(a, b), f4add(cc, d)),
                                   f4add(f4add(e, f), f4add(g, h))));
            }
            for (; i + 4 <= deg; i += 4) {
                int4 nn = *reinterpret_cast<const int4*>(&nb[i]);
                float4 a = z4[(size_t)nn.x * 32 + c];
                float4 b = z4[(size_t)nn.y * 32 + c];
                float4 cc = z4[(size_t)nn.z * 32 + c];
                float4 d = z4[(size_t)nn.w * 32 + c];
                s = f4add(s, f4add(f4add(a, b), f4add(cc, d)));
            }
            for (; i < deg; i++)
                s = f4add(s, z4[(size_t)nb[i] * 32 + c]);

            float dinv = (deg > 0) ? (1.0f / (float)deg) : 0.0f;
            float4 rr = r4[(size_t)t * 32 + c];
            float4 o;
            o.x = fmaxf(s.x * dinv + rr.x, 0.f);
            o.y = fmaxf(s.y * dinv + rr.y, 0.f);
            o.z = fmaxf(s.z * dinv + rr.z, 0.f);
            o.w = fmaxf(s.w * dinv + rr.w, 0.f);
            h4[(size_t)t * 32 + c] = o;
        }
    }
    __syncthreads();

    // ---- Phase 2: gemm 128 x VC, K=128, BK=8, double buffered ----
    int tx = tid & 31;          // TN cols each
    int ty = tid >> 5;          // 8 rows each

    // Loaders: A tile 128x8 = 256 float4 (threads < 256);
    //          B tile VC x 8 = VC*2 float4 (all threads if VC=256, else < 256).
    int lm = tid >> 1;          // row (A) / virtual B row
    int lkq = tid & 1;          // which float4 within BK=8
    bool aLd = (tid < 256);
    bool bLd = (VC == 256) ? true : (tid < 256);
    const float* aRow = &g_h[(size_t)(rowBase + lm) * 128 + lkq * 4];
    const float* bRow = (lm < fout) ? &Wl[(size_t)lm * 128 + lkq * 4]
                                    : &Wr[(size_t)(lm - fout) * 128 + lkq * 4];

    float acc[8][TN];
#pragma unroll
    for (int i = 0; i < 8; i++)
#pragma unroll
        for (int j = 0; j < TN; j++) acc[i][j] = 0.0f;

    float4 pa = make_float4(0.f, 0.f, 0.f, 0.f);
    float4 pb = make_float4(0.f, 0.f, 0.f, 0.f);
    if (aLd) pa = *reinterpret_cast<const float4*>(aRow);
    if (bLd) pb = *reinterpret_cast<const float4*>(bRow);
    if (aLd) {
        As[0][lkq * 4 + 0][lm] = pa.x; As[0][lkq * 4 + 1][lm] = pa.y;
        As[0][lkq * 4 + 2][lm] = pa.z; As[0][lkq * 4 + 3][lm] = pa.w;
    }
    if (bLd) {
        Bs[0][lkq * 4 + 0][lm] = pb.x; Bs[0][lkq * 4 + 1][lm] = pb.y;
        Bs[0][lkq * 4 + 2][lm] = pb.z; Bs[0][lkq * 4 + 3][lm] = pb.w;
    }
    __syncthreads();

#pragma unroll 1
    for (int kt = 0; kt < 16; kt++) {
        int buf = kt & 1;
        if (kt < 15) {
            if (aLd) pa = *reinterpret_cast<const float4*>(aRow + (kt + 1) * 8);
            if (bLd) pb = *reinterpret_cast<const float4*>(bRow + (kt + 1) * 8);
        }
#pragma unroll
        for (int kk = 0; kk < 8; kk++) {
            float4 a0 = *reinterpret_cast<float4*>(&As[buf][kk][ty * 8]);
            float4 a1 = *reinterpret_cast<float4*>(&As[buf][kk][ty * 8 + 4]);
            float am[8] = {a0.x, a0.y, a0.z, a0.w, a1.x, a1.y, a1.z, a1.w};
            float bn[TN];
            float4 b0 = *reinterpret_cast<float4*>(&Bs[buf][kk][tx * TN]);
            bn[0] = b0.x; bn[1] = b0.y; bn[2] = b0.z; bn[3] = b0.w;
            if (TN == 8) {
                float4 b1 = *reinterpret_cast<float4*>(&Bs[buf][kk][tx * TN + 4]);
                bn[4] = b1.x; bn[5] = b1.y; bn[6] = b1.z; bn[7] = b1.w;
            }
#pragma unroll
            for (int i = 0; i < 8; i++)
#pragma unroll
                for (int j = 0; j < TN; j++)
                    acc[i][j] = fmaf(am[i], bn[j], acc[i][j]);
        }
        if (kt < 15) {
            int nb = buf ^ 1;
            if (aLd) {
                As[nb][lkq * 4 + 0][lm] = pa.x; As[nb][lkq * 4 + 1][lm] = pa.y;
                As[nb][lkq * 4 + 2][lm] = pa.z; As[nb][lkq * 4 + 3][lm] = pa.w;
            }
            if (bLd) {
                Bs[nb][lkq * 4 + 0][lm] = pb.x; Bs[nb][lkq * 4 + 1][lm] = pb.y;
                Bs[nb][lkq * 4 + 2][lm] = pb.z; Bs[nb][lkq * 4 + 3][lm] = pb.w;
            }
            __syncthreads();
        }
    }

    // Epilogue: per float4 group, route to z or r (+bias, no relu here).
#pragma unroll
    for (int g = 0; g < TN / 4; g++) {
        int ovc = tx * TN + g * 4;
        bool isR = (ovc >= fout);
        int col = isR ? (ovc - fout) : ovc;
        float* dst = isR ? rbuf(zout) : zbuf(zout);
        float4 bv = make_float4(0.f, 0.f, 0.f, 0.f);
        if (isR) bv = *reinterpret_cast<const float4*>(&bias[col]);
#pragma unroll
        for (int i = 0; i < 8; i++) {
            int m = rowBase + ty * 8 + i;
            float4 o;
            o.x = acc[i][g * 4 + 0] + bv.x;
            o.y = acc[i][g * 4 + 1] + bv.y;
            o.z = acc[i][g * 4 + 2] + bv.z;
            o.w = acc[i][g * 4 + 3] + bv.w;
            *reinterpret_cast<float4*>(&dst[(size_t)m * fout + col]) = o;
        }
    }
}

// Final gather (F=64, no relu): out[t] = mean(z2[nbr]) + r2[t]
__global__ void gather64_kernel(float* __restrict__ out) {
    int t = blockIdx.x * 16 + (threadIdx.x >> 4);
    int c = threadIdx.x & 15;

    int deg = min(g_cnt[t], CAP);
    const int* nb = &g_nbr[t * CAP];
    const float4* z4 = reinterpret_cast<const float4*>(g_z2);

    float4 s = make_float4(0.f, 0.f, 0.f, 0.f);
    int i = 0;
    for (; i + 4 <= deg; i += 4) {
        int4 nn = *reinterpret_cast<const int4*>(&nb[i]);
        float4 a = z4[(size_t)nn.x * 16 + c];
        float4 b = z4[(size_t)nn.y * 16 + c];
        float4 cc = z4[(size_t)nn.z * 16 + c];
        float4 d = z4[(size_t)nn.w * 16 + c];
        s = f4add(s, f4add(f4add(a, b), f4add(cc, d)));
    }
    for (; i < deg; i++)
        s = f4add(s, z4[(size_t)nb[i] * 16 + c]);

    float dinv = (deg > 0) ? (1.0f / (float)deg) : 0.0f;
    float4 rr = reinterpret_cast<const float4*>(g_r2)[(size_t)t * 16 + c];
    float4 o;
    o.x = s.x * dinv + rr.x;
    o.y = s.y * dinv + rr.y;
    o.z = s.z * dinv + rr.z;
    o.w = s.w * dinv + rr.w;
    reinterpret_cast<float4*>(out)[(size_t)t * 16 + c] = o;
}

extern "C" void kernel_launch(void* const* d_in, const int* in_sizes, int n_in,
                              void* d_out, int out_size) {
    const float* x   = (const float*)d_in[0];
    const float* adj = (const float*)d_in[1];
    const float* Wl0 = (const float*)d_in[2];
    const float* b0  = (const float*)d_in[3];
    const float* Wr0 = (const float*)d_in[4];
    const float* Wl1 = (const float*)d_in[5];
    const float* b1  = (const float*)d_in[6];
    const float* Wr1 = (const float*)d_in[7];
    const float* Wl2 = (const float*)d_in[8];
    const float* b2  = (const float*)d_in[9];
    const float* Wr2 = (const float*)d_in[10];
    float* out = (float*)d_out;

    zero_cnt_kernel<<<NN / 256, 256>>>();

    // K2: layer-0 transform (x -> z0,r0) + full adjacency scan (R11-proven)
    fused_gemm0_build_kernel<<<1024 + 32768, 256>>>(x, adj, Wl0, Wr0, b0);

    // K3: layer 1 = gather(z0,r0)->h1 then gemm -> z1,r1  (phase-fused)
    fused_layer_kernel<256><<<128, 512>>>(Wl1, Wr1, b1, 128, 0, 1);

    // K4: layer 2 = gather(z1,r1)->h2 then gemm -> z2,r2  (phase-fused)
    fused_layer_kernel<128><<<128, 512>>>(Wl2, Wr2, b2, 64, 1, 2);

    // K5: final gather -> d_out (no relu)
    gather64_kernel<<<1024, 256>>>(out);
}

// round 14
// speedup vs baseline: 1.0930x; 1.0930x over previous
#include <cuda_runtime.h>

#define NN 16384
#define CAP 96
#define SPAD 132

// Scratch (no allocations). Referenced ONLY from device code.
__device__ int   g_cnt[NN];
__device__ int   g_nbr[NN * CAP];
__device__ float g_z[NN * 128];
__device__ float g_r[NN * 128];
__device__ float g_h[NN * 128];

__global__ void zero_cnt_kernel() {
    int i = blockIdx.x * blockDim.x + threadIdx.x;
    if (i < NN) g_cnt[i] = 0;
}

// ---------------------------------------------------------------------------
// LOW-REG GEMM block (layer 0 only, hidden under adj scan):
// 64x64 tile of x[N,128] @ [Wl0|Wr0]^T (fout=128). BK=32, 256 thr, TM4xTN4.
// ~42 regs so the fused kernel's scan blocks keep high occupancy.
// ---------------------------------------------------------------------------
__device__ __forceinline__ void gemm_block_small(
    const float* __restrict__ A,
    const float* __restrict__ Wl, const float* __restrict__ Wr,
    const float* __restrict__ bias, int rb, int cb,
    float (*As)[64], float (*Bs)[64])
{
    const int fout = 128;
    int tid = threadIdx.x;
    int rowBase = rb * 64;
    int vcol = cb * 64;

    const float* B;
    float* out;
    int colBase;
    bool addb;
    if (vcol < fout) { B = Wl; out = g_z; colBase = vcol;        addb = false; }
    else             { B = Wr; out = g_r; colBase = vcol - fout; addb = true;  }

    int tx = tid & 15;
    int ty = tid >> 4;

    float acc[4][4];
#pragma unroll
    for (int i = 0; i < 4; i++)
#pragma unroll
        for (int j = 0; j < 4; j++) acc[i][j] = 0.0f;

#pragma unroll 1
    for (int kt = 0; kt < 4; kt++) {
        int koff = kt * 32;
#pragma unroll
        for (int i = 0; i < 2; i++) {
            int lin = tid + i * 256;
            int m = lin >> 3;
            int kq = lin & 7;
            float4 v = *reinterpret_cast<const float4*>(
                &A[(size_t)(rowBase + m) * 128 + koff + kq * 4]);
            As[kq * 4 + 0][m] = v.x;
            As[kq * 4 + 1][m] = v.y;
            As[kq * 4 + 2][m] = v.z;
            As[kq * 4 + 3][m] = v.w;
        }
#pragma unroll
        for (int i = 0; i < 2; i++) {
            int lin = tid + i * 256;
            int o = lin >> 3;
            int kq = lin & 7;
            float4 v = *reinterpret_cast<const float4*>(
                &B[(size_t)(colBase + o) * 128 + koff + kq * 4]);
            Bs[kq * 4 + 0][o] = v.x;
            Bs[kq * 4 + 1][o] = v.y;
            Bs[kq * 4 + 2][o] = v.z;
            Bs[kq * 4 + 3][o] = v.w;
        }
        __syncthreads();

#pragma unroll
        for (int kk = 0; kk < 32; kk++) {
            float4 a0 = *reinterpret_cast<float4*>(&As[kk][ty * 4]);
            float4 b0 = *reinterpret_cast<float4*>(&Bs[kk][tx * 4]);
            float am[4] = {a0.x, a0.y, a0.z, a0.w};
            float bn[4] = {b0.x, b0.y, b0.z, b0.w};
#pragma unroll
            for (int i = 0; i < 4; i++)
#pragma unroll
                for (int j = 0; j < 4; j++)
                    acc[i][j] = fmaf(am[i], bn[j], acc[i][j]);
        }
        __syncthreads();
    }

#pragma unroll
    for (int i = 0; i < 4; i++) {
        int m = rowBase + ty * 4 + i;
        int o = colBase + tx * 4;
        float4 v;
        v.x = acc[i][0]; v.y = acc[i][1]; v.z = acc[i][2]; v.w = acc[i][3];
        if (addb) {
            float4 bv = *reinterpret_cast<const float4*>(&bias[o]);
            v.x += bv.x; v.y += bv.y; v.z += bv.z; v.w += bv.w;
        }
        *reinterpret_cast<float4*>(&out[(size_t)m * fout + o]) = v;
    }
}

// ---------------------------------------------------------------------------
// Fused kernel (R11-proven): blocks [0,1024) = layer-0 transform (lean regs);
// blocks [1024, 1024+32768) scan the 1 GB adj (32 KB contiguous per block).
// ---------------------------------------------------------------------------
__global__ void __launch_bounds__(256) fused_gemm0_build_kernel(
    const float* __restrict__ x, const float* __restrict__ adj,
    const float* __restrict__ Wl0, const float* __restrict__ Wr0,
    const float* __restrict__ b0)
{
    __shared__ float As[32][64];
    __shared__ float Bs[32][64];

    int bid = blockIdx.x;
    if (bid < 1024) {
        gemm_block_small(x, Wl0, Wr0, b0, bid >> 2, bid & 3, As, Bs);
        return;
    }

    int bb = bid - 1024;
    const float4* adj4 = reinterpret_cast<const float4*>(adj);
    size_t base = (size_t)bb * 2048 + threadIdx.x;

    float4 v[8];
#pragma unroll
    for (int i = 0; i < 8; i++) v[i] = __ldcs(&adj4[base + (size_t)i * 256]);

#pragma unroll
    for (int i = 0; i < 8; i++) {
        size_t idx = base + (size_t)i * 256;
        int r  = (int)(idx >> 12);          // 4096 float4 per adj row
        int c0 = (int)((idx & 4095) << 2);
        if (v[i].x != 0.0f) { int s = atomicAdd(&g_cnt[c0 + 0], 1); if (s < CAP) g_nbr[(c0 + 0) * CAP + s] = r; }
        if (v[i].y != 0.0f) { int s = atomicAdd(&g_cnt[c0 + 1], 1); if (s < CAP) g_nbr[(c0 + 1) * CAP + s] = r; }
        if (v[i].z != 0.0f) { int s = atomicAdd(&g_cnt[c0 + 2], 1); if (s < CAP) g_nbr[(c0 + 2) * CAP + s] = r; }
        if (v[i].w != 0.0f) { int s = atomicAdd(&g_cnt[c0 + 3], 1); if (s < CAP) g_nbr[(c0 + 3) * CAP + s] = r; }
    }
}

// ---------------------------------------------------------------------------
// Double-buffered SGEMM (layers 1 & 2): 128x128 tile, BK=8, TM8xTN8.
// Improvements vs R11: SINGLE __syncthreads per k-tile (the post-compute
// barrier is redundant under double buffering), and register-level fragment
// pipelining (next-kk LDS issued while current kk's FFMAs execute).
// ---------------------------------------------------------------------------
__global__ void __launch_bounds__(256, 2) gemm_kernel(
    const float* __restrict__ Wl, const float* __restrict__ Wr,
    const float* __restrict__ bias, int fout)
{
    __shared__ float As[2][8][SPAD];
    __shared__ float Bs[2][8][SPAD];
    const float* A = g_h;

    int tid = threadIdx.x;
    int rowBase = blockIdx.x * 128;
    int cbase = blockIdx.y * 128;

    int tx = tid & 15;
    int ty = tid >> 4;

    int lm = tid >> 1;
    int lkq = tid & 1;
    const float* aRow = &A[(size_t)(rowBase + lm) * 128 + lkq * 4];
    int ov = cbase + lm;
    const float* bRow = (ov < fout) ? &Wl[(size_t)ov * 128 + lkq * 4]
                                    : &Wr[(size_t)(ov - fout) * 128 + lkq * 4];

    float acc[8][8];
#pragma unroll
    for (int i = 0; i < 8; i++)
#pragma unroll
        for (int j = 0; j < 8; j++) acc[i][j] = 0.0f;

    float4 pa = *reinterpret_cast<const float4*>(aRow);
    float4 pb = *reinterpret_cast<const float4*>(bRow);
    As[0][lkq * 4 + 0][lm] = pa.x; As[0][lkq * 4 + 1][lm] = pa.y;
    As[0][lkq * 4 + 2][lm] = pa.z; As[0][lkq * 4 + 3][lm] = pa.w;
    Bs[0][lkq * 4 + 0][lm] = pb.x; Bs[0][lkq * 4 + 1][lm] = pb.y;
    Bs[0][lkq * 4 + 2][lm] = pb.z; Bs[0][lkq * 4 + 3][lm] = pb.w;
    __syncthreads();

#pragma unroll 1
    for (int kt = 0; kt < 16; kt++) {
        int buf = kt & 1;
        if (kt < 15) {
            pa = *reinterpret_cast<const float4*>(aRow + (kt + 1) * 8);
            pb = *reinterpret_cast<const float4*>(bRow + (kt + 1) * 8);
        }

        // Fragment-pipelined inner loop: prefetch kk+1 while computing kk.
        float4 a0 = *reinterpret_cast<float4*>(&As[buf][0][ty * 4]);
        float4 a1 = *reinterpret_cast<float4*>(&As[buf][0][64 + ty * 4]);
        float4 b0 = *reinterpret_cast<float4*>(&Bs[buf][0][tx * 4]);
        float4 b1 = *reinterpret_cast<float4*>(&Bs[buf][0][64 + tx * 4]);
#pragma unroll
        for (int kk = 0; kk < 8; kk++) {
            float4 na0, na1, nb0, nb1;
            if (kk < 7) {
                na0 = *reinterpret_cast<float4*>(&As[buf][kk + 1][ty * 4]);
                na1 = *reinterpret_cast<float4*>(&As[buf][kk + 1][64 + ty * 4]);
                nb0 = *reinterpret_cast<float4*>(&Bs[buf][kk + 1][tx * 4]);
                nb1 = *reinterpret_cast<float4*>(&Bs[buf][kk + 1][64 + tx * 4]);
            }
            float am[8] = {a0.x, a0.y, a0.z, a0.w, a1.x, a1.y, a1.z, a1.w};
            float bn[8] = {b0.x, b0.y, b0.z, b0.w, b1.x, b1.y, b1.z, b1.w};
#pragma unroll
            for (int i = 0; i < 8; i++)
#pragma unroll
                for (int j = 0; j < 8; j++)
                    acc[i][j] = fmaf(am[i], bn[j], acc[i][j]);
            if (kk < 7) { a0 = na0; a1 = na1; b0 = nb0; b1 = nb1; }
        }

        if (kt < 15) {
            int nb = buf ^ 1;
            As[nb][lkq * 4 + 0][lm] = pa.x; As[nb][lkq * 4 + 1][lm] = pa.y;
            As[nb][lkq * 4 + 2][lm] = pa.z; As[nb][lkq * 4 + 3][lm] = pa.w;
            Bs[nb][lkq * 4 + 0][lm] = pb.x; Bs[nb][lkq * 4 + 1][lm] = pb.y;
            Bs[nb][lkq * 4 + 2][lm] = pb.z; Bs[nb][lkq * 4 + 3][lm] = pb.w;
            __syncthreads();
        }
    }

#pragma unroll
    for (int g = 0; g < 2; g++) {
        int ovc = cbase + g * 64 + tx * 4;
        bool isR = (ovc >= fout);
        int col = isR ? (ovc - fout) : ovc;
        float* dst = isR ? g_r : g_z;
        float4 bv = make_float4(0.f, 0.f, 0.f, 0.f);
        if (isR) bv = *reinterpret_cast<const float4*>(&bias[col]);
#pragma unroll
        for (int h = 0; h < 2; h++) {
#pragma unroll
            for (int i = 0; i < 4; i++) {
                int m = rowBase + h * 64 + ty * 4 + i;
                float4 o;
                o.x = acc[h * 4 + i][g * 4 + 0] + bv.x;
                o.y = acc[h * 4 + i][g * 4 + 1] + bv.y;
                o.z = acc[h * 4 + i][g * 4 + 2] + bv.z;
                o.w = acc[h * 4 + i][g * 4 + 3] + bv.w;
                *reinterpret_cast<float4*>(&dst[(size_t)m * fout + col]) = o;
            }
        }
    }
}

__device__ __forceinline__ float4 f4add(float4 a, float4 b) {
    return make_float4(a.x + b.x, a.y + b.y, a.z + b.z, a.w + b.w);
}

// ---------------------------------------------------------------------------
// Gather: h[t] = act( deginv[t] * sum_{n in nbr(t)} z[n]  +  r[t] )
// ---------------------------------------------------------------------------
template <int F, bool RELU>
__global__ void gather_kernel(float* __restrict__ out_ext, int sel_out) {
    constexpr int TPT = F / 4;
    constexpr int TGT_PER_BLK = 128 / TPT;

    float* out = (sel_out == 0) ? out_ext : g_h;
    int lin = threadIdx.x;
    int t = blockIdx.x * TGT_PER_BLK + lin / TPT;
    int c = lin % TPT;

    int deg = min(g_cnt[t], CAP);
    const int* nb = &g_nbr[t * CAP];
    const float4* z4 = reinterpret_cast<const float4*>(g_z);

    float4 s = make_float4(0.f, 0.f, 0.f, 0.f);
    int i = 0;
    for (; i + 4 <= deg; i += 4) {
        int4 nn = *reinterpret_cast<const int4*>(&nb[i]);
        float4 a = z4[(size_t)nn.x * TPT + c];
        float4 b = z4[(size_t)nn.y * TPT + c];
        float4 cc = z4[(size_t)nn.z * TPT + c];
        float4 d = z4[(size_t)nn.w * TPT + c];
        s = f4add(s, f4add(f4add(a, b), f4add(cc, d)));
    }
    for (; i < deg; i++)
        s = f4add(s, z4[(size_t)nb[i] * TPT + c]);

    float dinv = (deg > 0) ? (1.0f / (float)deg) : 0.0f;
    float4 rr = reinterpret_cast<const float4*>(g_r)[(size_t)t * TPT + c];
    float4 o;
    o.x = s.x * dinv + rr.x;
    o.y = s.y * dinv + rr.y;
    o.z = s.z * dinv + rr.z;
    o.w = s.w * dinv + rr.w;
    if (RELU) {
        o.x = fmaxf(o.x, 0.f); o.y = fmaxf(o.y, 0.f);
        o.z = fmaxf(o.z, 0.f); o.w = fmaxf(o.w, 0.f);
    }
    reinterpret_cast<float4*>(out)[(size_t)t * TPT + c] = o;
}

extern "C" void kernel_launch(void* const* d_in, const int* in_sizes, int n_in,
                              void* d_out, int out_size) {
    const float* x   = (const float*)d_in[0];
    const float* adj = (const float*)d_in[1];
    const float* Wl0 = (const float*)d_in[2];
    const float* b0  = (const float*)d_in[3];
    const float* Wr0 = (const float*)d_in[4];
    const float* Wl1 = (const float*)d_in[5];
    const float* b1  = (const float*)d_in[6];
    const float* Wr1 = (const float*)d_in[7];
    const float* Wl2 = (const float*)d_in[8];
    const float* b2  = (const float*)d_in[9];
    const float* Wr2 = (const float*)d_in[10];
    float* out = (float*)d_out;

    zero_cnt_kernel<<<NN / 256, 256>>>();

    // Layer-0 transform (x -> z,r) overlapped with adjacency scan (lean regs).
    fused_gemm0_build_kernel<<<1024 + 32768, 256>>>(x, adj, Wl0, Wr0, b0);

    // Layer 0 aggregate+activate: g_h = relu(mean(z) + r)
    gather_kernel<128, true><<<NN / 4, 128>>>(nullptr, 1);

    // Layer 1 (virtual cols = 256 -> 2 col blocks)
    gemm_kernel<<<dim3(NN / 128, 2), 256>>>(Wl1, Wr1, b1, 128);
    gather_kernel<128, true><<<NN / 4, 128>>>(nullptr, 1);

    // Layer 2 (fout = 64, virtual cols = 128 -> 1 col block); final gather -> d_out
    gemm_kernel<<<dim3(NN / 128, 1), 256>>>(Wl2, Wr2, b2, 64);
    gather_kernel<64, false><<<NN / 8, 128>>>(out, 0);
}

// round 15
// speedup vs baseline: 1.1130x; 1.0183x over previous
#include <cuda_runtime.h>
#include <cstdint>

#define NN 16384
#define CAP 96
#define SK 36   // 32 k-floats + 4 pad: frag bank = 4*row + k, conflict-free

// Scratch (no allocations). Referenced ONLY from device code.
__device__ int   g_cnt[NN];
__device__ int   g_nbr[NN * CAP];
__device__ float g_z[NN * 128];
__device__ float g_r[NN * 128];
__device__ float g_h[NN * 128];

__global__ void zero_cnt_kernel() {
    int i = blockIdx.x * blockDim.x + threadIdx.x;
    if (i < NN) g_cnt[i] = 0;
}

// ---------------------------------------------------------------------------
// LOW-REG GEMM block (layer 0 only, hidden under adj scan, fp32, ~42 regs)
// ---------------------------------------------------------------------------
__device__ __forceinline__ void gemm_block_small(
    const float* __restrict__ A,
    const float* __restrict__ Wl, const float* __restrict__ Wr,
    const float* __restrict__ bias, int rb, int cb,
    float (*As)[64], float (*Bs)[64])
{
    const int fout = 128;
    int tid = threadIdx.x;
    int rowBase = rb * 64;
    int vcol = cb * 64;

    const float* B;
    float* out;
    int colBase;
    bool addb;
    if (vcol < fout) { B = Wl; out = g_z; colBase = vcol;        addb = false; }
    else             { B = Wr; out = g_r; colBase = vcol - fout; addb = true;  }

    int tx = tid & 15;
    int ty = tid >> 4;

    float acc[4][4];
#pragma unroll
    for (int i = 0; i < 4; i++)
#pragma unroll
        for (int j = 0; j < 4; j++) acc[i][j] = 0.0f;

#pragma unroll 1
    for (int kt = 0; kt < 4; kt++) {
        int koff = kt * 32;
#pragma unroll
        for (int i = 0; i < 2; i++) {
            int lin = tid + i * 256;
            int m = lin >> 3;
            int kq = lin & 7;
            float4 v = *reinterpret_cast<const float4*>(
                &A[(size_t)(rowBase + m) * 128 + koff + kq * 4]);
            As[kq * 4 + 0][m] = v.x;
            As[kq * 4 + 1][m] = v.y;
            As[kq * 4 + 2][m] = v.z;
            As[kq * 4 + 3][m] = v.w;
        }
#pragma unroll
        for (int i = 0; i < 2; i++) {
            int lin = tid + i * 256;
            int o = lin >> 3;
            int kq = lin & 7;
            float4 v = *reinterpret_cast<const float4*>(
                &B[(size_t)(colBase + o) * 128 + koff + kq * 4]);
            Bs[kq * 4 + 0][o] = v.x;
            Bs[kq * 4 + 1][o] = v.y;
            Bs[kq * 4 + 2][o] = v.z;
            Bs[kq * 4 + 3][o] = v.w;
        }
        __syncthreads();

#pragma unroll
        for (int kk = 0; kk < 32; kk++) {
            float4 a0 = *reinterpret_cast<float4*>(&As[kk][ty * 4]);
            float4 b0 = *reinterpret_cast<float4*>(&Bs[kk][tx * 4]);
            float am[4] = {a0.x, a0.y, a0.z, a0.w};
            float bn[4] = {b0.x, b0.y, b0.z, b0.w};
#pragma unroll
            for (int i = 0; i < 4; i++)
#pragma unroll
                for (int j = 0; j < 4; j++)
                    acc[i][j] = fmaf(am[i], bn[j], acc[i][j]);
        }
        __syncthreads();
    }

#pragma unroll
    for (int i = 0; i < 4; i++) {
        int m = rowBase + ty * 4 + i;
        int o = colBase + tx * 4;
        float4 v;
        v.x = acc[i][0]; v.y = acc[i][1]; v.z = acc[i][2]; v.w = acc[i][3];
        if (addb) {
            float4 bv = *reinterpret_cast<const float4*>(&bias[o]);
            v.x += bv.x; v.y += bv.y; v.z += bv.z; v.w += bv.w;
        }
        *reinterpret_cast<float4*>(&out[(size_t)m * fout + o]) = v;
    }
}

// ---------------------------------------------------------------------------
// Fused kernel (R11-proven): blocks [0,1024) = layer-0 transform (lean regs);
// blocks [1024, 1024+32768) scan the 1 GB adj (32 KB contiguous per block).
// ---------------------------------------------------------------------------
__global__ void __launch_bounds__(256) fused_gemm0_build_kernel(
    const float* __restrict__ x, const float* __restrict__ adj,
    const float* __restrict__ Wl0, const float* __restrict__ Wr0,
    const float* __restrict__ b0)
{
    __shared__ float As[32][64];
    __shared__ float Bs[32][64];

    int bid = blockIdx.x;
    if (bid < 1024) {
        gemm_block_small(x, Wl0, Wr0, b0, bid >> 2, bid & 3, As, Bs);
        return;
    }

    int bb = bid - 1024;
    const float4* adj4 = reinterpret_cast<const float4*>(adj);
    size_t base = (size_t)bb * 2048 + threadIdx.x;

    float4 v[8];
#pragma unroll
    for (int i = 0; i < 8; i++) v[i] = __ldcs(&adj4[base + (size_t)i * 256]);

#pragma unroll
    for (int i = 0; i < 8; i++) {
        size_t idx = base + (size_t)i * 256;
        int r  = (int)(idx >> 12);          // 4096 float4 per adj row
        int c0 = (int)((idx & 4095) << 2);
        if (v[i].x != 0.0f) { int s = atomicAdd(&g_cnt[c0 + 0], 1); if (s < CAP) g_nbr[(c0 + 0) * CAP + s] = r; }
        if (v[i].y != 0.0f) { int s = atomicAdd(&g_cnt[c0 + 1], 1); if (s < CAP) g_nbr[(c0 + 1) * CAP + s] = r; }
        if (v[i].z != 0.0f) { int s = atomicAdd(&g_cnt[c0 + 2], 1); if (s < CAP) g_nbr[(c0 + 2) * CAP + s] = r; }
        if (v[i].w != 0.0f) { int s = atomicAdd(&g_cnt[c0 + 3], 1); if (s < CAP) g_nbr[(c0 + 3) * CAP + s] = r; }
    }
}

// ---------------------------------------------------------------------------
// tf32 tensor-core helpers
// ---------------------------------------------------------------------------
__device__ __forceinline__ uint32_t f2tf32(float x) {
    uint32_t r;
    asm("cvt.rna.tf32.f32 %0, %1;" : "=r"(r) : "f"(x));
    return r;
}

__device__ __forceinline__ void mma_tf32(float* c,
    uint32_t a0, uint32_t a1, uint32_t a2, uint32_t a3,
    uint32_t b0, uint32_t b1)
{
    asm volatile(
        "mma.sync.aligned.m16n8k8.row.col.f32.tf32.tf32.f32 "
        "{%0,%1,%2,%3}, {%4,%5,%6,%7}, {%8,%9}, {%0,%1,%2,%3};\n"
        : "+f"(c[0]), "+f"(c[1]), "+f"(c[2]), "+f"(c[3])
        : "r"(a0), "r"(a1), "r"(a2), "r"(a3), "r"(b0), "r"(b1));
}

// ---------------------------------------------------------------------------
// TF32 GEMM (layers 1 & 2), 3xTF32 split for fp32-grade accuracy:
//   D = h @ Bv^T, Bv row ov: ov < fout -> Wl[ov] (out g_z), else Wr (g_r, +b)
// Block: 256 thr, tile 128 rows x 64 virtual cols, K=128 (4 k-tiles of 32).
// Warps: 4(m) x 2(n); warp tile 32x32 = (2 mt) x (4 nt) m16n8k8 frags.
// Smem stride SK=36: frag loads bank-conflict-free.
// ---------------------------------------------------------------------------
__global__ void __launch_bounds__(256, 2) gemm_tf32_kernel(
    const float* __restrict__ Wl, const float* __restrict__ Wr,
    const float* __restrict__ bias, int fout)
{
    __shared__ float As[128][SK];
    __shared__ float Bs[64][SK];

    int tid = threadIdx.x;
    int rowBase = blockIdx.x * 128;
    int cbase = blockIdx.y * 64;

    int w = tid >> 5, lane = tid & 31;
    int g = lane >> 2, t4 = lane & 3;
    int warpM = (w >> 1) * 32;
    int warpN = (w & 1) * 32;

    // Global source pointers for the staged tiles.
    const float4* aP[4];
    float* aS[4];
#pragma unroll
    for (int i = 0; i < 4; i++) {
        int lin = tid + i * 256;
        int row = lin >> 3, kq = lin & 7;
        aP[i] = reinterpret_cast<const float4*>(
            g_h + (size_t)(rowBase + row) * 128 + kq * 4);
        aS[i] = &As[row][kq * 4];
    }
    const float4* bP[2];
    float* bS[2];
#pragma unroll
    for (int i = 0; i < 2; i++) {
        int lin = tid + i * 256;
        int n = lin >> 3, kq = lin & 7;
        int ov = cbase + n;
        const float* basep = (ov < fout) ? (Wl + (size_t)ov * 128)
                                         : (Wr + (size_t)(ov - fout) * 128);
        bP[i] = reinterpret_cast<const float4*>(basep + kq * 4);
        bS[i] = &Bs[n][kq * 4];
    }

    float c[2][4][4];
#pragma unroll
    for (int mt = 0; mt < 2; mt++)
#pragma unroll
        for (int nt = 0; nt < 4; nt++)
#pragma unroll
            for (int q = 0; q < 4; q++) c[mt][nt][q] = 0.0f;

    float4 pa[4], pb[2];
    // Stage k-tile 0
#pragma unroll
    for (int i = 0; i < 4; i++) pa[i] = aP[i][0];
#pragma unroll
    for (int i = 0; i < 2; i++) pb[i] = bP[i][0];
#pragma unroll
    for (int i = 0; i < 4; i++) *reinterpret_cast<float4*>(aS[i]) = pa[i];
#pragma unroll
    for (int i = 0; i < 2; i++) *reinterpret_cast<float4*>(bS[i]) = pb[i];
    __syncthreads();

#pragma unroll 1
    for (int kt = 0; kt < 4; kt++) {
        if (kt < 3) {
#pragma unroll
            for (int i = 0; i < 4; i++) pa[i] = aP[i][(kt + 1) * 8];
#pragma unroll
            for (int i = 0; i < 2; i++) pb[i] = bP[i][(kt + 1) * 8];
        }

#pragma unroll
        for (int ks = 0; ks < 4; ks++) {
            int k0 = ks * 8 + t4;

            uint32_t ah[2][4], al[2][4];
#pragma unroll
            for (int mt = 0; mt < 2; mt++) {
                int m = warpM + mt * 16 + g;
                float o0 = As[m][k0];
                float o1 = As[m + 8][k0];
                float o2 = As[m][k0 + 4];
                float o3 = As[m + 8][k0 + 4];
                ah[mt][0] = f2tf32(o0); al[mt][0] = __float_as_uint(o0 - __uint_as_float(ah[mt][0]));
                ah[mt][1] = f2tf32(o1); al[mt][1] = __float_as_uint(o1 - __uint_as_float(ah[mt][1]));
                ah[mt][2] = f2tf32(o2); al[mt][2] = __float_as_uint(o2 - __uint_as_float(ah[mt][2]));
                ah[mt][3] = f2tf32(o3); al[mt][3] = __float_as_uint(o3 - __uint_as_float(ah[mt][3]));
            }
            uint32_t bh[4][2], bl[4][2];
#pragma unroll
            for (int nt = 0; nt < 4; nt++) {
                int n = warpN + nt * 8 + g;
                float o0 = Bs[n][k0];
                float o1 = Bs[n][k0 + 4];
                bh[nt][0] = f2tf32(o0); bl[nt][0] = __float_as_uint(o0 - __uint_as_float(bh[nt][0]));
                bh[nt][1] = f2tf32(o1); bl[nt][1] = __float_as_uint(o1 - __uint_as_float(bh[nt][1]));
            }

#pragma unroll
            for (int mt = 0; mt < 2; mt++)
#pragma unroll
                for (int nt = 0; nt < 4; nt++) {
                    mma_tf32(c[mt][nt], ah[mt][0], ah[mt][1], ah[mt][2], ah[mt][3],
                             bl[nt][0], bl[nt][1]);
                    mma_tf32(c[mt][nt], al[mt][0], al[mt][1], al[mt][2], al[mt][3],
                             bh[nt][0], bh[nt][1]);
                    mma_tf32(c[mt][nt], ah[mt][0], ah[mt][1], ah[mt][2], ah[mt][3],
                             bh[nt][0], bh[nt][1]);
                }
        }

        if (kt < 3) {
            __syncthreads();
#pragma unroll
            for (int i = 0; i < 4; i++) *reinterpret_cast<float4*>(aS[i]) = pa[i];
#pragma unroll
            for (int i = 0; i < 2; i++) *reinterpret_cast<float4*>(bS[i]) = pb[i];
            __syncthreads();
        }
    }

    // Epilogue: c[mt][nt] -> (row, vcol) with z/r routing (+bias on r half).
#pragma unroll
    for (int mt = 0; mt < 2; mt++) {
#pragma unroll
        for (int nt = 0; nt < 4; nt++) {
            int row0 = rowBase + warpM + mt * 16 + g;
            int vcol = cbase + warpN + nt * 8 + t4 * 2;
            bool isR = (vcol >= fout);
            int col = isR ? (vcol - fout) : vcol;
            float* dst = isR ? g_r : g_z;
            float b0v = 0.f, b1v = 0.f;
            if (isR) { b0v = bias[col]; b1v = bias[col + 1]; }
            float2 v0 = make_float2(c[mt][nt][0] + b0v, c[mt][nt][1] + b1v);
            float2 v1 = make_float2(c[mt][nt][2] + b0v, c[mt][nt][3] + b1v);
            *reinterpret_cast<float2*>(&dst[(size_t)row0 * fout + col]) = v0;
            *reinterpret_cast<float2*>(&dst[(size_t)(row0 + 8) * fout + col]) = v1;
        }
    }
}

__device__ __forceinline__ float4 f4add(float4 a, float4 b) {
    return make_float4(a.x + b.x, a.y + b.y, a.z + b.z, a.w + b.w);
}

// ---------------------------------------------------------------------------
// Gather: h[t] = act( deginv[t] * sum_{n in nbr(t)} z[n]  +  r[t] )
// ---------------------------------------------------------------------------
template <int F, bool RELU>
__global__ void gather_kernel(float* __restrict__ out_ext, int sel_out) {
    constexpr int TPT = F / 4;
    constexpr int TGT_PER_BLK = 128 / TPT;

    float* out = (sel_out == 0) ? out_ext : g_h;
    int lin = threadIdx.x;
    int t = blockIdx.x * TGT_PER_BLK + lin / TPT;
    int c = lin % TPT;

    int deg = min(g_cnt[t], CAP);
    const int* nb = &g_nbr[t * CAP];
    const float4* z4 = reinterpret_cast<const float4*>(g_z);

    float4 s = make_float4(0.f, 0.f, 0.f, 0.f);
    int i = 0;
    for (; i + 4 <= deg; i += 4) {
        int4 nn = *reinterpret_cast<const int4*>(&nb[i]);
        float4 a = z4[(size_t)nn.x * TPT + c];
        float4 b = z4[(size_t)nn.y * TPT + c];
        float4 cc = z4[(size_t)nn.z * TPT + c];
        float4 d = z4[(size_t)nn.w * TPT + c];
        s = f4add(s, f4add(f4add(a, b), f4add(cc, d)));
    }
    for (; i < deg; i++)
        s = f4add(s, z4[(size_t)nb[i] * TPT + c]);

    float dinv = (deg > 0) ? (1.0f / (float)deg) : 0.0f;
    float4 rr = reinterpret_cast<const float4*>(g_r)[(size_t)t * TPT + c];
    float4 o;
    o.x = s.x * dinv + rr.x;
    o.y = s.y * dinv + rr.y;
    o.z = s.z * dinv + rr.z;
    o.w = s.w * dinv + rr.w;
    if (RELU) {
        o.x = fmaxf(o.x, 0.f); o.y = fmaxf(o.y, 0.f);
        o.z = fmaxf(o.z, 0.f); o.w = fmaxf(o.w, 0.f);
    }
    reinterpret_cast<float4*>(out)[(size_t)t * TPT + c] = o;
}

extern "C" void kernel_launch(void* const* d_in, const int* in_sizes, int n_in,
                              void* d_out, int out_size) {
    const float* x   = (const float*)d_in[0];
    const float* adj = (const float*)d_in[1];
    const float* Wl0 = (const float*)d_in[2];
    const float* b0  = (const float*)d_in[3];
    const float* Wr0 = (const float*)d_in[4];
    const float* Wl1 = (const float*)d_in[5];
    const float* b1  = (const float*)d_in[6];
    const float* Wr1 = (const float*)d_in[7];
    const float* Wl2 = (const float*)d_in[8];
    const float* b2  = (const float*)d_in[9];
    const float* Wr2 = (const float*)d_in[10];
    float* out = (float*)d_out;

    zero_cnt_kernel<<<NN / 256, 256>>>();

    // Layer-0 transform (x -> z,r) overlapped with adjacency scan (lean regs).
    fused_gemm0_build_kernel<<<1024 + 32768, 256>>>(x, adj, Wl0, Wr0, b0);

    // Layer 0 aggregate+activate: g_h = relu(mean(z) + r)
    gather_kernel<128, true><<<NN / 4, 128>>>(nullptr, 1);

    // Layer 1 (virtual cols = 256 -> 4 col blocks of 64), tf32 tensor cores
    gemm_tf32_kernel<<<dim3(NN / 128, 4), 256>>>(Wl1, Wr1, b1, 128);
    gather_kernel<128, true><<<NN / 4, 128>>>(nullptr, 1);

    // Layer 2 (fout = 64, virtual cols = 128 -> 2 col blocks), tf32
    gemm_tf32_kernel<<<dim3(NN / 128, 2), 256>>>(Wl2, Wr2, b2, 64);
    gather_kernel<64, false><<<NN / 8, 128>>>(out, 0);
}